// round 11
// baseline (speedup 1.0000x reference)
#include <cuda_runtime.h>
#include <cuda_bf16.h>
#include <math.h>
#include <stdint.h>

#define NTOK 4096   // B*T
#define DDIM 1024
#define FDIM 4096
#define NEXP 8
#define NROWS (NTOK * 2)   // dispatch rows (top-2)

// GEMM tiling: 256x128 CTA tile, K-chunk 16, 2-stage smem double buffer
#define BM  256
#define KCH 16
#define APITCH 48                    // 16 bf16 = 32B padded to 48B (odd 16B units)
#define BPITCH 272                   // 128 bf16 = 256B padded to 272B
#define A_TILE (BM * APITCH)         // 12288 per half (hi or lo)
#define B_TILE (KCH * BPITCH)        // 4352 per half
#define STAGE  (2 * A_TILE + 2 * B_TILE)  // 33280
#define SMEM_BYTES (2 * STAGE)       // 66560 (dynamic, opt-in)

// ---------------- device scratch (~210MB, proven) ----------------
__device__ int   g_count[NEXP];
__device__ int   g_cursor[NEXP];
__device__ int   g_offset[NEXP];
__device__ int   g_topk_idx[NTOK * 2];
__device__ float g_topk_w[NTOK * 2];
__device__ int   g_token_of_row[NROWS];
__device__ float g_w_of_row[NROWS];
__device__ int   g_row_of_token[NROWS];
__device__ __align__(16) __nv_bfloat16 g_Xhi[(size_t)NROWS * DDIM];  // 16 MB
__device__ __align__(16) __nv_bfloat16 g_Xlo[(size_t)NROWS * DDIM];  // 16 MB
__device__ __align__(16) __nv_bfloat16 g_Hhi[(size_t)NROWS * FDIM];  // 64 MB
__device__ __align__(16) __nv_bfloat16 g_Hlo[(size_t)NROWS * FDIM];  // 64 MB
__device__ __align__(16) float         g_Y[(size_t)NROWS * DDIM];    // 33.5 MB

// ---------------- helpers ----------------
__device__ __forceinline__ uint32_t smem_u32(const void* p) {
    uint32_t a;
    asm("{ .reg .u64 t; cvta.to.shared.u64 t, %1; cvt.u32.u64 %0, t; }" : "=r"(a) : "l"(p));
    return a;
}
__device__ __forceinline__ void ldm_x4(uint32_t (&r)[4], uint32_t a) {
    asm volatile("ldmatrix.sync.aligned.m8n8.x4.shared.b16 {%0,%1,%2,%3}, [%4];"
                 : "=r"(r[0]), "=r"(r[1]), "=r"(r[2]), "=r"(r[3]) : "r"(a));
}
__device__ __forceinline__ void ldm_x4t(uint32_t (&r)[4], uint32_t a) {
    asm volatile("ldmatrix.sync.aligned.m8n8.x4.trans.shared.b16 {%0,%1,%2,%3}, [%4];"
                 : "=r"(r[0]), "=r"(r[1]), "=r"(r[2]), "=r"(r[3]) : "r"(a));
}
__device__ __forceinline__ void mma16816(float (&d)[4], const uint32_t (&a)[4],
                                         uint32_t b0, uint32_t b1) {
    asm volatile("mma.sync.aligned.m16n8k16.row.col.f32.bf16.bf16.f32 "
                 "{%0,%1,%2,%3}, {%4,%5,%6,%7}, {%8,%9}, {%0,%1,%2,%3};"
                 : "+f"(d[0]), "+f"(d[1]), "+f"(d[2]), "+f"(d[3])
                 : "r"(a[0]), "r"(a[1]), "r"(a[2]), "r"(a[3]), "r"(b0), "r"(b1));
}
__device__ __forceinline__ uint32_t pk2(__nv_bfloat16 a, __nv_bfloat16 b) {
    return (uint32_t)__bfloat16_as_ushort(a) | ((uint32_t)__bfloat16_as_ushort(b) << 16);
}
__device__ __forceinline__ float gelu_exact(float v) {
    return 0.5f * v * (1.0f + erff(v * 0.70710678118654752440f));
}
__device__ __forceinline__ void split8(float4 v0, float4 v1, uint4& hi, uint4& lo) {
    __nv_bfloat16 h0 = __float2bfloat16(v0.x), h1 = __float2bfloat16(v0.y);
    __nv_bfloat16 h2 = __float2bfloat16(v0.z), h3 = __float2bfloat16(v0.w);
    __nv_bfloat16 h4 = __float2bfloat16(v1.x), h5 = __float2bfloat16(v1.y);
    __nv_bfloat16 h6 = __float2bfloat16(v1.z), h7 = __float2bfloat16(v1.w);
    hi.x = pk2(h0, h1); hi.y = pk2(h2, h3); hi.z = pk2(h4, h5); hi.w = pk2(h6, h7);
    lo.x = pk2(__float2bfloat16(v0.x - __bfloat162float(h0)),
               __float2bfloat16(v0.y - __bfloat162float(h1)));
    lo.y = pk2(__float2bfloat16(v0.z - __bfloat162float(h2)),
               __float2bfloat16(v0.w - __bfloat162float(h3)));
    lo.z = pk2(__float2bfloat16(v1.x - __bfloat162float(h4)),
               __float2bfloat16(v1.y - __bfloat162float(h5)));
    lo.w = pk2(__float2bfloat16(v1.z - __bfloat162float(h6)),
               __float2bfloat16(v1.w - __bfloat162float(h7)));
}

// ---------------- K0-K3: routing (unchanged, proven) ----------------
__global__ void zero_kernel() {
    int t = threadIdx.x;
    if (t < NEXP) { g_count[t] = 0; g_cursor[t] = 0; }
}

__global__ void router_kernel(const float* __restrict__ x,
                              const float* __restrict__ Wr) {
    int gwarp  = (blockIdx.x * blockDim.x + threadIdx.x) >> 5;
    int lane   = threadIdx.x & 31;
    int nwarps = (gridDim.x * blockDim.x) >> 5;
    for (int n = gwarp; n < NTOK; n += nwarps) {
        const float* xr = x + (size_t)n * DDIM;
        float acc[NEXP];
        #pragma unroll
        for (int e = 0; e < NEXP; e++) acc[e] = 0.f;
        for (int d = lane; d < DDIM; d += 32) {
            float xv = xr[d];
            const float* wr = Wr + (size_t)d * NEXP;
            float4 w0 = *(const float4*)(wr);
            float4 w1 = *(const float4*)(wr + 4);
            acc[0] = fmaf(xv, w0.x, acc[0]); acc[1] = fmaf(xv, w0.y, acc[1]);
            acc[2] = fmaf(xv, w0.z, acc[2]); acc[3] = fmaf(xv, w0.w, acc[3]);
            acc[4] = fmaf(xv, w1.x, acc[4]); acc[5] = fmaf(xv, w1.y, acc[5]);
            acc[6] = fmaf(xv, w1.z, acc[6]); acc[7] = fmaf(xv, w1.w, acc[7]);
        }
        #pragma unroll
        for (int e = 0; e < NEXP; e++)
            #pragma unroll
            for (int o = 16; o > 0; o >>= 1)
                acc[e] += __shfl_xor_sync(0xFFFFFFFFu, acc[e], o);
        if (lane == 0) {
            int i0 = 0; float v0 = acc[0];
            #pragma unroll
            for (int e = 1; e < NEXP; e++)
                if (acc[e] > v0) { v0 = acc[e]; i0 = e; }
            int i1 = -1; float v1 = -3.4e38f;
            #pragma unroll
            for (int e = 0; e < NEXP; e++)
                if (e != i0 && acc[e] > v1) { v1 = acc[e]; i1 = e; }
            float e1 = __expf(v1 - v0);
            float inv = 1.0f / (1.0f + e1);
            g_topk_idx[2 * n + 0] = i0;
            g_topk_idx[2 * n + 1] = i1;
            g_topk_w[2 * n + 0] = inv;
            g_topk_w[2 * n + 1] = e1 * inv;
            atomicAdd(&g_count[i0], 1);
            atomicAdd(&g_count[i1], 1);
        }
    }
}

__global__ void prefix_kernel() {
    int s = 0;
    for (int e = 0; e < NEXP; e++) { g_offset[e] = s; s += g_count[e]; }
}

__global__ void dispatch_kernel() {
    int n = blockIdx.x * blockDim.x + threadIdx.x;
    if (n >= NTOK) return;
    #pragma unroll
    for (int s = 0; s < 2; s++) {
        int e   = g_topk_idx[2 * n + s];
        int pos = atomicAdd(&g_cursor[e], 1);
        int row = g_offset[e] + pos;
        g_token_of_row[row] = n;
        g_w_of_row[row]     = g_topk_w[2 * n + s];
        g_row_of_token[2 * n + s] = row;
    }
}

// ---------------- K4: gather + split X -> bf16 hi/lo ----------------
__global__ void gather_split_x_kernel(const float* __restrict__ x) {
    int r = blockIdx.x;
    int t = g_token_of_row[r];
    float4 v = ((const float4*)(x + (size_t)t * DDIM))[threadIdx.x];
    __nv_bfloat16 h0 = __float2bfloat16(v.x), h1 = __float2bfloat16(v.y);
    __nv_bfloat16 h2 = __float2bfloat16(v.z), h3 = __float2bfloat16(v.w);
    __nv_bfloat16 l0 = __float2bfloat16(v.x - __bfloat162float(h0));
    __nv_bfloat16 l1 = __float2bfloat16(v.y - __bfloat162float(h1));
    __nv_bfloat16 l2 = __float2bfloat16(v.z - __bfloat162float(h2));
    __nv_bfloat16 l3 = __float2bfloat16(v.w - __bfloat162float(h3));
    ((uint2*)(g_Xhi + (size_t)r * DDIM))[threadIdx.x] = make_uint2(pk2(h0, h1), pk2(h2, h3));
    ((uint2*)(g_Xlo + (size_t)r * DDIM))[threadIdx.x] = make_uint2(pk2(l0, l1), pk2(l2, l3));
}

// ---------------- GEMM: split-bf16 mma.sync, 256x128 tile, 8 warps -------
// warp grid 4x2 (wm 0..3, wn 0..1), warp tile 64m x 64n, acc[4][8][4]
// PH1: H(bf16 hi/lo) = gelu(Xsplit @ W1[e]), grid (m, n, e)
// PH2: Y = w * (Hsplit @ W2[e]),             grid (n, m, e)
template<bool PH1>
__global__ __launch_bounds__(256) void moe_gemm_kernel(const float* __restrict__ Wglob) {
    constexpr int K  = PH1 ? DDIM : FDIM;
    constexpr int NT = PH1 ? FDIM : DDIM;
    constexpr int NC = K / KCH;

    const int e   = blockIdx.z;
    const int cnt = g_count[e];
    const int m0  = (PH1 ? blockIdx.x : blockIdx.y) * BM;
    if (m0 >= cnt) return;
    const int n0  = (PH1 ? blockIdx.y : blockIdx.x) * 128;
    const int off = g_offset[e];
    const size_t rowbase = (size_t)off + m0;
    const float* Bsrc = Wglob + (size_t)e * K * NT + n0;

    extern __shared__ __align__(128) char smbuf[];   // 2 * STAGE
    __shared__ float wrow[BM];

    const int tid  = threadIdx.x;
    const int warp = tid >> 5, lane = tid & 31;
    const int wm = warp & 3, wn = warp >> 2;    // 4x2 warps: 64m x 64n each

    if (!PH1) {
        int r = m0 + tid;
        wrow[tid] = (r < cnt) ? g_w_of_row[off + r] : 0.f;
    }

    // loader roles: A one full 32B row per thread; B 16 k-rows x 16 segs(8 elems)
    const int a_row = tid;                     // 256 rows
    const int b_k   = tid >> 4, b_seg = tid & 15;

    size_t ra = rowbase + a_row;
    if (ra >= NROWS) ra = 0;   // clamp (discarded via epilogue bounds)
    const __nv_bfloat16* aptrH = (PH1 ? g_Xhi : g_Hhi) + ra * (size_t)K;
    const __nv_bfloat16* aptrL = (PH1 ? g_Xlo : g_Hlo) + ra * (size_t)K;

    // prefetch registers (A pre-split bf16: 32B hi + 32B lo; B 8 fp32)
    uint4  pah0, pah1, pal0, pal1;
    float4 pb0, pb1;
    auto prefetch = [&](int kc) {
        pah0 = *(const uint4*)(aptrH + kc);
        pah1 = *(const uint4*)(aptrH + kc + 8);
        pal0 = *(const uint4*)(aptrL + kc);
        pal1 = *(const uint4*)(aptrL + kc + 8);
        pb0 = *(const float4*)(Bsrc + (size_t)(kc + b_k) * NT + b_seg * 8);
        pb1 = *(const float4*)(Bsrc + (size_t)(kc + b_k) * NT + b_seg * 8 + 4);
    };
    auto store_stage = [&](int stg) {
        char* dst = smbuf + stg * STAGE;
        *(uint4*)(dst + a_row * APITCH)           = pah0;
        *(uint4*)(dst + a_row * APITCH + 16)      = pah1;
        *(uint4*)(dst + A_TILE + a_row * APITCH)      = pal0;
        *(uint4*)(dst + A_TILE + a_row * APITCH + 16) = pal1;
        uint4 hi, lo;
        split8(pb0, pb1, hi, lo);
        *(uint4*)(dst + 2 * A_TILE + b_k * BPITCH + b_seg * 16) = hi;
        *(uint4*)(dst + 2 * A_TILE + B_TILE + b_k * BPITCH + b_seg * 16) = lo;
    };

    prefetch(0);
    store_stage(0);

    float acc[4][8][4];
    #pragma unroll
    for (int i = 0; i < 4; i++)
        #pragma unroll
        for (int j = 0; j < 8; j++)
            #pragma unroll
            for (int q = 0; q < 4; q++) acc[i][j][q] = 0.f;

    const uint32_t smb = smem_u32(smbuf);
    const int lrow = lane & 15;
    const int lk   = lane >> 4;
    const uint32_t aoff = (uint32_t)((wm * 64 + lrow) * APITCH + lk * 16);
    const uint32_t boff = (uint32_t)(2 * A_TILE + lrow * BPITCH + wn * 128 + lk * 16);

    #pragma unroll 1
    for (int c = 0; c < NC; c++) {
        if (c + 1 < NC) prefetch((c + 1) * KCH);   // issue LDG before barrier
        __syncthreads();   // stage c&1 stores visible; stage (c+1)&1 readers done

        uint32_t stb = smb + (uint32_t)((c & 1) * STAGE);
        uint32_t bh[4][4], bl[4][4];
        #pragma unroll
        for (int p = 0; p < 4; p++) {
            uint32_t b = stb + boff + p * 32;
            ldm_x4t(bh[p], b);
            ldm_x4t(bl[p], b + B_TILE);
        }
        #pragma unroll
        for (int mi = 0; mi < 4; mi++) {
            uint32_t ah[4], al[4];
            uint32_t a = stb + aoff + mi * (16 * APITCH);
            ldm_x4(ah, a);
            ldm_x4(al, a + A_TILE);
            #pragma unroll
            for (int ni = 0; ni < 8; ni++) {
                int p = ni >> 1, q = (ni & 1) * 2;
                mma16816(acc[mi][ni], ah, bh[p][q], bh[p][q + 1]);
                mma16816(acc[mi][ni], ah, bl[p][q], bl[p][q + 1]);
                mma16816(acc[mi][ni], al, bh[p][q], bh[p][q + 1]);
            }
        }
        if (c + 1 < NC) store_stage((c + 1) & 1);
    }

    // ---------------- epilogue ----------------
    const int ro  = lane >> 2;
    const int cp2 = (lane & 3) * 2;
    #pragma unroll
    for (int mi = 0; mi < 4; mi++)
        #pragma unroll
        for (int half = 0; half < 2; half++) {
            int lr = wm * 64 + mi * 16 + half * 8 + ro;
            if (m0 + lr < cnt) {
                size_t gr = rowbase + lr;
                if (PH1) {
                    __nv_bfloat16* oh = g_Hhi + gr * (size_t)FDIM + n0 + wn * 64 + cp2;
                    __nv_bfloat16* ol = g_Hlo + gr * (size_t)FDIM + n0 + wn * 64 + cp2;
                    #pragma unroll
                    for (int ni = 0; ni < 8; ni++) {
                        float f0 = gelu_exact(acc[mi][ni][half * 2 + 0]);
                        float f1 = gelu_exact(acc[mi][ni][half * 2 + 1]);
                        __nv_bfloat16 h0 = __float2bfloat16(f0), h1 = __float2bfloat16(f1);
                        __nv_bfloat16 l0 = __float2bfloat16(f0 - __bfloat162float(h0));
                        __nv_bfloat16 l1 = __float2bfloat16(f1 - __bfloat162float(h1));
                        *(uint32_t*)(oh + ni * 8) = pk2(h0, h1);
                        *(uint32_t*)(ol + ni * 8) = pk2(l0, l1);
                    }
                } else {
                    float w = wrow[lr];
                    float* od = g_Y + gr * (size_t)DDIM + n0 + wn * 64 + cp2;
                    #pragma unroll
                    for (int ni = 0; ni < 8; ni++) {
                        float2 v;
                        v.x = w * acc[mi][ni][half * 2 + 0];
                        v.y = w * acc[mi][ni][half * 2 + 1];
                        *(float2*)(od + ni * 8) = v;
                    }
                }
            }
        }
}

// ---------------- combine ----------------
__global__ void combine_kernel(float* __restrict__ out) {
    int idx = blockIdx.x * blockDim.x + threadIdx.x;
    if (idx >= NTOK * (DDIM / 4)) return;
    int n  = idx >> 8;
    int d4 = idx & 255;
    int r0 = g_row_of_token[2 * n + 0];
    int r1 = g_row_of_token[2 * n + 1];
    float4 a = *(const float4*)(g_Y + (size_t)r0 * DDIM + d4 * 4);
    float4 b = *(const float4*)(g_Y + (size_t)r1 * DDIM + d4 * 4);
    float4 o;
    o.x = a.x + b.x; o.y = a.y + b.y; o.z = a.z + b.z; o.w = a.w + b.w;
    ((float4*)out)[idx] = o;
}

// ---------------- launch ----------------
extern "C" void kernel_launch(void* const* d_in, const int* in_sizes, int n_in,
                              void* d_out, int out_size) {
    const float* x  = (const float*)d_in[0];
    const float* Wr = (const float*)d_in[1];
    const float* W1 = (const float*)d_in[2];   // [E][D][F]
    const float* W2 = (const float*)d_in[3];   // [E][F][D]
    float* out = (float*)d_out;

    cudaFuncSetAttribute(moe_gemm_kernel<true>,
                         cudaFuncAttributeMaxDynamicSharedMemorySize, SMEM_BYTES);
    cudaFuncSetAttribute(moe_gemm_kernel<false>,
                         cudaFuncAttributeMaxDynamicSharedMemorySize, SMEM_BYTES);

    zero_kernel<<<1, 32>>>();
    router_kernel<<<64, 256>>>(x, Wr);
    prefix_kernel<<<1, 1>>>();
    dispatch_kernel<<<(NTOK + 255) / 256, 256>>>();
    gather_split_x_kernel<<<NROWS, 256>>>(x);
    moe_gemm_kernel<true><<<dim3(NROWS / BM, FDIM / 128, NEXP), 256, SMEM_BYTES>>>(W1);
    moe_gemm_kernel<false><<<dim3(DDIM / 128, NROWS / BM, NEXP), 256, SMEM_BYTES>>>(W2);
    combine_kernel<<<(NTOK * (DDIM / 4) + 255) / 256, 256>>>(out);
}

// round 12
// speedup vs baseline: 1.2951x; 1.2951x over previous
#include <cuda_runtime.h>
#include <cuda_bf16.h>
#include <math.h>
#include <stdint.h>

#define NTOK 4096   // B*T
#define DDIM 1024
#define FDIM 4096
#define NEXP 8
#define NROWS (NTOK * 2)   // dispatch rows (top-2)

// GEMM tiling: 128x128 CTA tile, K-chunk 16, 2-stage smem double buffer (static)
#define KCH 16
#define APITCH 48                    // 16 bf16 = 32B padded to 48B (odd 16B units)
#define BPITCH 272                   // 128 bf16 = 256B padded to 272B
#define A_TILE (128 * APITCH)        // 6144 per half (hi or lo)
#define B_TILE (KCH * BPITCH)        // 4352 per half
#define STAGE  (2 * A_TILE + 2 * B_TILE)  // 20992

// ---------------- device scratch (~210MB, proven) ----------------
__device__ int   g_count[NEXP];
__device__ int   g_cursor[NEXP];
__device__ int   g_offset[NEXP];
__device__ int   g_topk_idx[NTOK * 2];
__device__ float g_topk_w[NTOK * 2];
__device__ int   g_token_of_row[NROWS];
__device__ float g_w_of_row[NROWS];
__device__ int   g_row_of_token[NROWS];
__device__ __align__(16) __nv_bfloat16 g_Xhi[(size_t)NROWS * DDIM];  // 16 MB
__device__ __align__(16) __nv_bfloat16 g_Xlo[(size_t)NROWS * DDIM];  // 16 MB
__device__ __align__(16) __nv_bfloat16 g_Hhi[(size_t)NROWS * FDIM];  // 64 MB
__device__ __align__(16) __nv_bfloat16 g_Hlo[(size_t)NROWS * FDIM];  // 64 MB
__device__ __align__(16) float         g_Y[(size_t)NROWS * DDIM];    // 33.5 MB

// ---------------- helpers ----------------
__device__ __forceinline__ uint32_t smem_u32(const void* p) {
    uint32_t a;
    asm("{ .reg .u64 t; cvta.to.shared.u64 t, %1; cvt.u32.u64 %0, t; }" : "=r"(a) : "l"(p));
    return a;
}
__device__ __forceinline__ void ldm_x4(uint32_t (&r)[4], uint32_t a) {
    asm volatile("ldmatrix.sync.aligned.m8n8.x4.shared.b16 {%0,%1,%2,%3}, [%4];"
                 : "=r"(r[0]), "=r"(r[1]), "=r"(r[2]), "=r"(r[3]) : "r"(a));
}
__device__ __forceinline__ void ldm_x4t(uint32_t (&r)[4], uint32_t a) {
    asm volatile("ldmatrix.sync.aligned.m8n8.x4.trans.shared.b16 {%0,%1,%2,%3}, [%4];"
                 : "=r"(r[0]), "=r"(r[1]), "=r"(r[2]), "=r"(r[3]) : "r"(a));
}
__device__ __forceinline__ void mma16816(float (&d)[4], const uint32_t (&a)[4],
                                         uint32_t b0, uint32_t b1) {
    asm volatile("mma.sync.aligned.m16n8k16.row.col.f32.bf16.bf16.f32 "
                 "{%0,%1,%2,%3}, {%4,%5,%6,%7}, {%8,%9}, {%0,%1,%2,%3};"
                 : "+f"(d[0]), "+f"(d[1]), "+f"(d[2]), "+f"(d[3])
                 : "r"(a[0]), "r"(a[1]), "r"(a[2]), "r"(a[3]), "r"(b0), "r"(b1));
}
__device__ __forceinline__ uint32_t pk2(__nv_bfloat16 a, __nv_bfloat16 b) {
    return (uint32_t)__bfloat16_as_ushort(a) | ((uint32_t)__bfloat16_as_ushort(b) << 16);
}
__device__ __forceinline__ float gelu_exact(float v) {
    return 0.5f * v * (1.0f + erff(v * 0.70710678118654752440f));
}
// packed hi/lo split: 2 floats -> 1 packed bf16x2 hi + 1 packed bf16x2 lo
__device__ __forceinline__ void split2(float a, float b, uint32_t& hi, uint32_t& lo) {
    __nv_bfloat162 h = __floats2bfloat162_rn(a, b);          // 1 packed cvt
    float2 hf = __bfloat1622float2(h);                        // packed unpack
    __nv_bfloat162 l = __floats2bfloat162_rn(a - hf.x, b - hf.y);
    hi = *reinterpret_cast<uint32_t*>(&h);
    lo = *reinterpret_cast<uint32_t*>(&l);
}
__device__ __forceinline__ void split8(float4 v0, float4 v1, uint4& hi, uint4& lo) {
    split2(v0.x, v0.y, hi.x, lo.x);
    split2(v0.z, v0.w, hi.y, lo.y);
    split2(v1.x, v1.y, hi.z, lo.z);
    split2(v1.z, v1.w, hi.w, lo.w);
}

// ---------------- K0-K3: routing (unchanged, proven) ----------------
__global__ void zero_kernel() {
    int t = threadIdx.x;
    if (t < NEXP) { g_count[t] = 0; g_cursor[t] = 0; }
}

__global__ void router_kernel(const float* __restrict__ x,
                              const float* __restrict__ Wr) {
    int gwarp  = (blockIdx.x * blockDim.x + threadIdx.x) >> 5;
    int lane   = threadIdx.x & 31;
    int nwarps = (gridDim.x * blockDim.x) >> 5;
    for (int n = gwarp; n < NTOK; n += nwarps) {
        const float* xr = x + (size_t)n * DDIM;
        float acc[NEXP];
        #pragma unroll
        for (int e = 0; e < NEXP; e++) acc[e] = 0.f;
        for (int d = lane; d < DDIM; d += 32) {
            float xv = xr[d];
            const float* wr = Wr + (size_t)d * NEXP;
            float4 w0 = *(const float4*)(wr);
            float4 w1 = *(const float4*)(wr + 4);
            acc[0] = fmaf(xv, w0.x, acc[0]); acc[1] = fmaf(xv, w0.y, acc[1]);
            acc[2] = fmaf(xv, w0.z, acc[2]); acc[3] = fmaf(xv, w0.w, acc[3]);
            acc[4] = fmaf(xv, w1.x, acc[4]); acc[5] = fmaf(xv, w1.y, acc[5]);
            acc[6] = fmaf(xv, w1.z, acc[6]); acc[7] = fmaf(xv, w1.w, acc[7]);
        }
        #pragma unroll
        for (int e = 0; e < NEXP; e++)
            #pragma unroll
            for (int o = 16; o > 0; o >>= 1)
                acc[e] += __shfl_xor_sync(0xFFFFFFFFu, acc[e], o);
        if (lane == 0) {
            int i0 = 0; float v0 = acc[0];
            #pragma unroll
            for (int e = 1; e < NEXP; e++)
                if (acc[e] > v0) { v0 = acc[e]; i0 = e; }
            int i1 = -1; float v1 = -3.4e38f;
            #pragma unroll
            for (int e = 0; e < NEXP; e++)
                if (e != i0 && acc[e] > v1) { v1 = acc[e]; i1 = e; }
            float e1 = __expf(v1 - v0);
            float inv = 1.0f / (1.0f + e1);
            g_topk_idx[2 * n + 0] = i0;
            g_topk_idx[2 * n + 1] = i1;
            g_topk_w[2 * n + 0] = inv;
            g_topk_w[2 * n + 1] = e1 * inv;
            atomicAdd(&g_count[i0], 1);
            atomicAdd(&g_count[i1], 1);
        }
    }
}

__global__ void prefix_kernel() {
    int s = 0;
    for (int e = 0; e < NEXP; e++) { g_offset[e] = s; s += g_count[e]; }
}

__global__ void dispatch_kernel() {
    int n = blockIdx.x * blockDim.x + threadIdx.x;
    if (n >= NTOK) return;
    #pragma unroll
    for (int s = 0; s < 2; s++) {
        int e   = g_topk_idx[2 * n + s];
        int pos = atomicAdd(&g_cursor[e], 1);
        int row = g_offset[e] + pos;
        g_token_of_row[row] = n;
        g_w_of_row[row]     = g_topk_w[2 * n + s];
        g_row_of_token[2 * n + s] = row;
    }
}

// ---------------- K4: gather + split X -> bf16 hi/lo ----------------
__global__ void gather_split_x_kernel(const float* __restrict__ x) {
    int r = blockIdx.x;
    int t = g_token_of_row[r];
    float4 v = ((const float4*)(x + (size_t)t * DDIM))[threadIdx.x];
    uint32_t h0, h1, l0, l1;
    split2(v.x, v.y, h0, l0);
    split2(v.z, v.w, h1, l1);
    ((uint2*)(g_Xhi + (size_t)r * DDIM))[threadIdx.x] = make_uint2(h0, h1);
    ((uint2*)(g_Xlo + (size_t)r * DDIM))[threadIdx.x] = make_uint2(l0, l1);
}

// ---------------- GEMM: split-bf16 mma.sync (R9 config, slimmer issue) ----
// PH1: H(bf16 hi/lo) = gelu(Xsplit @ W1[e]), grid (m, n, e)
// PH2: Y = w * (Hsplit @ W2[e]),             grid (n, m, e)
template<bool PH1>
__global__ __launch_bounds__(256, 2) void moe_gemm_kernel(const float* __restrict__ Wglob) {
    constexpr int K  = PH1 ? DDIM : FDIM;
    constexpr int NT = PH1 ? FDIM : DDIM;
    constexpr int NC = K / KCH;

    const int e   = blockIdx.z;
    const int cnt = g_count[e];
    const int m0  = (PH1 ? blockIdx.x : blockIdx.y) * 128;
    if (m0 >= cnt) return;
    const int n0  = (PH1 ? blockIdx.y : blockIdx.x) * 128;
    const int off = g_offset[e];
    const size_t rowbase = (size_t)off + m0;
    const float* Bsrc = Wglob + (size_t)e * K * NT + n0;

    __shared__ __align__(128) char smbuf[2][STAGE];
    __shared__ float wrow[128];

    const int tid  = threadIdx.x;
    const int warp = tid >> 5, lane = tid & 31;
    const int wm = warp & 1, wn = warp >> 1;    // 2x4 warps: 64m x 32n each

    if (!PH1 && tid < 128) {
        int r = m0 + tid;
        wrow[tid] = (r < cnt) ? g_w_of_row[off + r] : 0.f;
    }

    // loader roles: A 128 rows x 2 segs(8 elems); B 16 k-rows x 16 segs(8 elems)
    const int a_row = tid >> 1, a_seg = tid & 1;
    const int b_k   = tid >> 4, b_seg = tid & 15;

    size_t ra = rowbase + a_row;
    if (ra >= NROWS) ra = 0;   // clamp (values discarded via epilogue bounds)
    const __nv_bfloat16* aptrH = (PH1 ? g_Xhi : g_Hhi) + ra * (size_t)K;
    const __nv_bfloat16* aptrL = (PH1 ? g_Xlo : g_Hlo) + ra * (size_t)K;

    // prefetch registers (A pre-split bf16; B fp32)
    uint4  pah, pal;
    float4 pb0, pb1;
    auto prefetch = [&](int kc) {
        pah = *(const uint4*)(aptrH + kc + a_seg * 8);
        pal = *(const uint4*)(aptrL + kc + a_seg * 8);
        pb0 = *(const float4*)(Bsrc + (size_t)(kc + b_k) * NT + b_seg * 8);
        pb1 = *(const float4*)(Bsrc + (size_t)(kc + b_k) * NT + b_seg * 8 + 4);
    };
    auto store_stage = [&](int stg) {
        char* dst = smbuf[stg];
        *(uint4*)(dst + a_row * APITCH + a_seg * 16) = pah;
        *(uint4*)(dst + A_TILE + a_row * APITCH + a_seg * 16) = pal;
        uint4 hi, lo;
        split8(pb0, pb1, hi, lo);
        *(uint4*)(dst + 2 * A_TILE + b_k * BPITCH + b_seg * 16) = hi;
        *(uint4*)(dst + 2 * A_TILE + B_TILE + b_k * BPITCH + b_seg * 16) = lo;
    };

    prefetch(0);
    store_stage(0);

    float acc[4][4][4];
    #pragma unroll
    for (int i = 0; i < 4; i++)
        #pragma unroll
        for (int j = 0; j < 4; j++)
            #pragma unroll
            for (int q = 0; q < 4; q++) acc[i][j][q] = 0.f;

    const uint32_t smb = smem_u32(smbuf);
    const int lrow = lane & 15;
    const int lk   = lane >> 4;
    const uint32_t aoff = (uint32_t)((wm * 64 + lrow) * APITCH + lk * 16);
    const uint32_t boff = (uint32_t)(2 * A_TILE + lrow * BPITCH + wn * 64 + lk * 16);

    #pragma unroll 1
    for (int c = 0; c < NC; c++) {
        if (c + 1 < NC) prefetch((c + 1) * KCH);   // issue LDG before barrier
        __syncthreads();   // stage c&1 stores visible; stage (c+1)&1 readers done

        uint32_t stb = smb + (uint32_t)((c & 1) * STAGE);
        uint32_t bh[2][4], bl[2][4];
        #pragma unroll
        for (int p = 0; p < 2; p++) {
            uint32_t b = stb + boff + p * 32;
            ldm_x4t(bh[p], b);
            ldm_x4t(bl[p], b + B_TILE);
        }
        #pragma unroll
        for (int mi = 0; mi < 4; mi++) {
            uint32_t ah[4], al[4];
            uint32_t a = stb + aoff + mi * (16 * APITCH);
            ldm_x4(ah, a);
            ldm_x4(al, a + A_TILE);
            #pragma unroll
            for (int ni = 0; ni < 4; ni++) {
                int p = ni >> 1, q = (ni & 1) * 2;
                mma16816(acc[mi][ni], ah, bh[p][q], bh[p][q + 1]);
                mma16816(acc[mi][ni], ah, bl[p][q], bl[p][q + 1]);
                mma16816(acc[mi][ni], al, bh[p][q], bh[p][q + 1]);
            }
        }
        if (c + 1 < NC) store_stage((c + 1) & 1);
    }

    // ---------------- epilogue ----------------
    const int ro  = lane >> 2;
    const int cp2 = (lane & 3) * 2;
    #pragma unroll
    for (int mi = 0; mi < 4; mi++)
        #pragma unroll
        for (int half = 0; half < 2; half++) {
            int lr = wm * 64 + mi * 16 + half * 8 + ro;
            if (m0 + lr < cnt) {
                size_t gr = rowbase + lr;
                if (PH1) {
                    __nv_bfloat16* oh = g_Hhi + gr * (size_t)FDIM + n0 + wn * 32 + cp2;
                    __nv_bfloat16* ol = g_Hlo + gr * (size_t)FDIM + n0 + wn * 32 + cp2;
                    #pragma unroll
                    for (int ni = 0; ni < 4; ni++) {
                        float f0 = gelu_exact(acc[mi][ni][half * 2 + 0]);
                        float f1 = gelu_exact(acc[mi][ni][half * 2 + 1]);
                        uint32_t h, l;
                        split2(f0, f1, h, l);
                        *(uint32_t*)(oh + ni * 8) = h;
                        *(uint32_t*)(ol + ni * 8) = l;
                    }
                } else {
                    float w = wrow[lr];
                    float* od = g_Y + gr * (size_t)DDIM + n0 + wn * 32 + cp2;
                    #pragma unroll
                    for (int ni = 0; ni < 4; ni++) {
                        float2 v;
                        v.x = w * acc[mi][ni][half * 2 + 0];
                        v.y = w * acc[mi][ni][half * 2 + 1];
                        *(float2*)(od + ni * 8) = v;
                    }
                }
            }
        }
}

// ---------------- combine ----------------
__global__ void combine_kernel(float* __restrict__ out) {
    int idx = blockIdx.x * blockDim.x + threadIdx.x;
    if (idx >= NTOK * (DDIM / 4)) return;
    int n  = idx >> 8;
    int d4 = idx & 255;
    int r0 = g_row_of_token[2 * n + 0];
    int r1 = g_row_of_token[2 * n + 1];
    float4 a = *(const float4*)(g_Y + (size_t)r0 * DDIM + d4 * 4);
    float4 b = *(const float4*)(g_Y + (size_t)r1 * DDIM + d4 * 4);
    float4 o;
    o.x = a.x + b.x; o.y = a.y + b.y; o.z = a.z + b.z; o.w = a.w + b.w;
    ((float4*)out)[idx] = o;
}

// ---------------- launch ----------------
extern "C" void kernel_launch(void* const* d_in, const int* in_sizes, int n_in,
                              void* d_out, int out_size) {
    const float* x  = (const float*)d_in[0];
    const float* Wr = (const float*)d_in[1];
    const float* W1 = (const float*)d_in[2];   // [E][D][F]
    const float* W2 = (const float*)d_in[3];   // [E][F][D]
    float* out = (float*)d_out;

    zero_kernel<<<1, 32>>>();
    router_kernel<<<64, 256>>>(x, Wr);
    prefix_kernel<<<1, 1>>>();
    dispatch_kernel<<<(NTOK + 255) / 256, 256>>>();
    gather_split_x_kernel<<<NROWS, 256>>>(x);
    moe_gemm_kernel<true><<<dim3(NROWS / 128, FDIM / 128, NEXP), 256>>>(W1);
    moe_gemm_kernel<false><<<dim3(DDIM / 128, NROWS / 128, NEXP), 256>>>(W2);
    combine_kernel<<<(NTOK * (DDIM / 4) + 255) / 256, 256>>>(out);
}

// round 13
// speedup vs baseline: 1.3639x; 1.0531x over previous
#include <cuda_runtime.h>
#include <cuda_bf16.h>
#include <math.h>
#include <stdint.h>

#define NTOK 4096   // B*T
#define DDIM 1024
#define FDIM 4096
#define NEXP 8
#define NROWS (NTOK * 2)   // dispatch rows (top-2)

// ---- GEMM1 tiling (bf16 3-term, proven R12) ----
#define KCH 16
#define APITCH 48                    // 16 bf16 = 32B padded to 48B (odd 16B units)
#define BPITCH 272                   // 128 bf16 = 256B padded to 272B
#define A_TILE (128 * APITCH)        // 6144 per half
#define B_TILE (KCH * BPITCH)        // 4352 per half
#define STAGE  (2 * A_TILE + 2 * B_TILE)  // 20992

// ---- GEMM2 tiling (tf32 single-pass) ----
#define PITCH2  80                   // 16 fp32 = 64B padded to 80B (odd 16B units)
#define A_TILE2 (128 * PITCH2)       // 10240
#define B_TILE2 (128 * PITCH2)       // 10240 ([n][k] transposed)
#define STAGE2  (A_TILE2 + B_TILE2)  // 20480

// ---------------- device scratch (~216MB) ----------------
__device__ int   g_count[NEXP];
__device__ int   g_cursor[NEXP];
__device__ int   g_offset[NEXP];
__device__ int   g_topk_idx[NTOK * 2];
__device__ float g_topk_w[NTOK * 2];
__device__ int   g_token_of_row[NROWS];
__device__ float g_w_of_row[NROWS];
__device__ int   g_row_of_token[NROWS];
__device__ __align__(16) __nv_bfloat16 g_Xhi[(size_t)NROWS * DDIM];  // 16 MB
__device__ __align__(16) __nv_bfloat16 g_Xlo[(size_t)NROWS * DDIM];  // 16 MB
__device__ __align__(16) float         g_H[(size_t)NROWS * FDIM];    // 134 MB (tf32-rounded)
__device__ __align__(16) float         g_Y[(size_t)NROWS * DDIM];    // 33.5 MB

// ---------------- helpers ----------------
__device__ __forceinline__ uint32_t smem_u32(const void* p) {
    uint32_t a;
    asm("{ .reg .u64 t; cvta.to.shared.u64 t, %1; cvt.u32.u64 %0, t; }" : "=r"(a) : "l"(p));
    return a;
}
__device__ __forceinline__ void ldm_x4(uint32_t (&r)[4], uint32_t a) {
    asm volatile("ldmatrix.sync.aligned.m8n8.x4.shared.b16 {%0,%1,%2,%3}, [%4];"
                 : "=r"(r[0]), "=r"(r[1]), "=r"(r[2]), "=r"(r[3]) : "r"(a));
}
__device__ __forceinline__ void ldm_x4t(uint32_t (&r)[4], uint32_t a) {
    asm volatile("ldmatrix.sync.aligned.m8n8.x4.trans.shared.b16 {%0,%1,%2,%3}, [%4];"
                 : "=r"(r[0]), "=r"(r[1]), "=r"(r[2]), "=r"(r[3]) : "r"(a));
}
__device__ __forceinline__ void mma16816(float (&d)[4], const uint32_t (&a)[4],
                                         uint32_t b0, uint32_t b1) {
    asm volatile("mma.sync.aligned.m16n8k16.row.col.f32.bf16.bf16.f32 "
                 "{%0,%1,%2,%3}, {%4,%5,%6,%7}, {%8,%9}, {%0,%1,%2,%3};"
                 : "+f"(d[0]), "+f"(d[1]), "+f"(d[2]), "+f"(d[3])
                 : "r"(a[0]), "r"(a[1]), "r"(a[2]), "r"(a[3]), "r"(b0), "r"(b1));
}
__device__ __forceinline__ void mma_tf32(float (&d)[4], const uint32_t (&a)[4],
                                         uint32_t b0, uint32_t b1) {
    asm volatile("mma.sync.aligned.m16n8k8.row.col.f32.tf32.tf32.f32 "
                 "{%0,%1,%2,%3}, {%4,%5,%6,%7}, {%8,%9}, {%0,%1,%2,%3};"
                 : "+f"(d[0]), "+f"(d[1]), "+f"(d[2]), "+f"(d[3])
                 : "r"(a[0]), "r"(a[1]), "r"(a[2]), "r"(a[3]), "r"(b0), "r"(b1));
}
__device__ __forceinline__ uint32_t cvt_tf32(float v) {
    uint32_t r;
    asm("cvt.rna.tf32.f32 %0, %1;" : "=r"(r) : "f"(v));
    return r;
}
__device__ __forceinline__ uint32_t pk2(__nv_bfloat16 a, __nv_bfloat16 b) {
    return (uint32_t)__bfloat16_as_ushort(a) | ((uint32_t)__bfloat16_as_ushort(b) << 16);
}
__device__ __forceinline__ float gelu_exact(float v) {
    return 0.5f * v * (1.0f + erff(v * 0.70710678118654752440f));
}
__device__ __forceinline__ void split2(float a, float b, uint32_t& hi, uint32_t& lo) {
    __nv_bfloat162 h = __floats2bfloat162_rn(a, b);
    float2 hf = __bfloat1622float2(h);
    __nv_bfloat162 l = __floats2bfloat162_rn(a - hf.x, b - hf.y);
    hi = *reinterpret_cast<uint32_t*>(&h);
    lo = *reinterpret_cast<uint32_t*>(&l);
}
__device__ __forceinline__ void split8(float4 v0, float4 v1, uint4& hi, uint4& lo) {
    split2(v0.x, v0.y, hi.x, lo.x);
    split2(v0.z, v0.w, hi.y, lo.y);
    split2(v1.x, v1.y, hi.z, lo.z);
    split2(v1.z, v1.w, hi.w, lo.w);
}

// ---------------- K0-K3: routing (unchanged, proven) ----------------
__global__ void zero_kernel() {
    int t = threadIdx.x;
    if (t < NEXP) { g_count[t] = 0; g_cursor[t] = 0; }
}

__global__ void router_kernel(const float* __restrict__ x,
                              const float* __restrict__ Wr) {
    int gwarp  = (blockIdx.x * blockDim.x + threadIdx.x) >> 5;
    int lane   = threadIdx.x & 31;
    int nwarps = (gridDim.x * blockDim.x) >> 5;
    for (int n = gwarp; n < NTOK; n += nwarps) {
        const float* xr = x + (size_t)n * DDIM;
        float acc[NEXP];
        #pragma unroll
        for (int e = 0; e < NEXP; e++) acc[e] = 0.f;
        for (int d = lane; d < DDIM; d += 32) {
            float xv = xr[d];
            const float* wr = Wr + (size_t)d * NEXP;
            float4 w0 = *(const float4*)(wr);
            float4 w1 = *(const float4*)(wr + 4);
            acc[0] = fmaf(xv, w0.x, acc[0]); acc[1] = fmaf(xv, w0.y, acc[1]);
            acc[2] = fmaf(xv, w0.z, acc[2]); acc[3] = fmaf(xv, w0.w, acc[3]);
            acc[4] = fmaf(xv, w1.x, acc[4]); acc[5] = fmaf(xv, w1.y, acc[5]);
            acc[6] = fmaf(xv, w1.z, acc[6]); acc[7] = fmaf(xv, w1.w, acc[7]);
        }
        #pragma unroll
        for (int e = 0; e < NEXP; e++)
            #pragma unroll
            for (int o = 16; o > 0; o >>= 1)
                acc[e] += __shfl_xor_sync(0xFFFFFFFFu, acc[e], o);
        if (lane == 0) {
            int i0 = 0; float v0 = acc[0];
            #pragma unroll
            for (int e = 1; e < NEXP; e++)
                if (acc[e] > v0) { v0 = acc[e]; i0 = e; }
            int i1 = -1; float v1 = -3.4e38f;
            #pragma unroll
            for (int e = 0; e < NEXP; e++)
                if (e != i0 && acc[e] > v1) { v1 = acc[e]; i1 = e; }
            float e1 = __expf(v1 - v0);
            float inv = 1.0f / (1.0f + e1);
            g_topk_idx[2 * n + 0] = i0;
            g_topk_idx[2 * n + 1] = i1;
            g_topk_w[2 * n + 0] = inv;
            g_topk_w[2 * n + 1] = e1 * inv;
            atomicAdd(&g_count[i0], 1);
            atomicAdd(&g_count[i1], 1);
        }
    }
}

__global__ void prefix_kernel() {
    int s = 0;
    for (int e = 0; e < NEXP; e++) { g_offset[e] = s; s += g_count[e]; }
}

__global__ void dispatch_kernel() {
    int n = blockIdx.x * blockDim.x + threadIdx.x;
    if (n >= NTOK) return;
    #pragma unroll
    for (int s = 0; s < 2; s++) {
        int e   = g_topk_idx[2 * n + s];
        int pos = atomicAdd(&g_cursor[e], 1);
        int row = g_offset[e] + pos;
        g_token_of_row[row] = n;
        g_w_of_row[row]     = g_topk_w[2 * n + s];
        g_row_of_token[2 * n + s] = row;
    }
}

// ---------------- K4: gather + split X -> bf16 hi/lo ----------------
__global__ void gather_split_x_kernel(const float* __restrict__ x) {
    int r = blockIdx.x;
    int t = g_token_of_row[r];
    float4 v = ((const float4*)(x + (size_t)t * DDIM))[threadIdx.x];
    uint32_t h0, h1, l0, l1;
    split2(v.x, v.y, h0, l0);
    split2(v.z, v.w, h1, l1);
    ((uint2*)(g_Xhi + (size_t)r * DDIM))[threadIdx.x] = make_uint2(h0, h1);
    ((uint2*)(g_Xlo + (size_t)r * DDIM))[threadIdx.x] = make_uint2(l0, l1);
}

// ---------------- GEMM1: split-bf16 mma.sync (R12 engine) -----------------
// H(fp32, tf32-rounded) = gelu(Xsplit @ W1[e]);  grid (m, n, e)
__global__ __launch_bounds__(256, 2) void moe_gemm1_kernel(const float* __restrict__ Wglob) {
    constexpr int K  = DDIM;
    constexpr int NT = FDIM;
    constexpr int NC = K / KCH;

    const int e   = blockIdx.z;
    const int cnt = g_count[e];
    const int m0  = blockIdx.x * 128;
    if (m0 >= cnt) return;
    const int n0  = blockIdx.y * 128;
    const int off = g_offset[e];
    const size_t rowbase = (size_t)off + m0;
    const float* Bsrc = Wglob + (size_t)e * K * NT + n0;

    __shared__ __align__(128) char smbuf[2][STAGE];

    const int tid  = threadIdx.x;
    const int warp = tid >> 5, lane = tid & 31;
    const int wm = warp & 1, wn = warp >> 1;

    const int a_row = tid >> 1, a_seg = tid & 1;
    const int b_k   = tid >> 4, b_seg = tid & 15;

    size_t ra = rowbase + a_row;
    if (ra >= NROWS) ra = 0;
    const __nv_bfloat16* aptrH = g_Xhi + ra * (size_t)K;
    const __nv_bfloat16* aptrL = g_Xlo + ra * (size_t)K;

    uint4  pah, pal;
    float4 pb0, pb1;
    auto prefetch = [&](int kc) {
        pah = *(const uint4*)(aptrH + kc + a_seg * 8);
        pal = *(const uint4*)(aptrL + kc + a_seg * 8);
        pb0 = *(const float4*)(Bsrc + (size_t)(kc + b_k) * NT + b_seg * 8);
        pb1 = *(const float4*)(Bsrc + (size_t)(kc + b_k) * NT + b_seg * 8 + 4);
    };
    auto store_stage = [&](int stg) {
        char* dst = smbuf[stg];
        *(uint4*)(dst + a_row * APITCH + a_seg * 16) = pah;
        *(uint4*)(dst + A_TILE + a_row * APITCH + a_seg * 16) = pal;
        uint4 hi, lo;
        split8(pb0, pb1, hi, lo);
        *(uint4*)(dst + 2 * A_TILE + b_k * BPITCH + b_seg * 16) = hi;
        *(uint4*)(dst + 2 * A_TILE + B_TILE + b_k * BPITCH + b_seg * 16) = lo;
    };

    prefetch(0);
    store_stage(0);

    float acc[4][4][4];
    #pragma unroll
    for (int i = 0; i < 4; i++)
        #pragma unroll
        for (int j = 0; j < 4; j++)
            #pragma unroll
            for (int q = 0; q < 4; q++) acc[i][j][q] = 0.f;

    const uint32_t smb = smem_u32(smbuf);
    const int lrow = lane & 15;
    const int lk   = lane >> 4;
    const uint32_t aoff = (uint32_t)((wm * 64 + lrow) * APITCH + lk * 16);
    const uint32_t boff = (uint32_t)(2 * A_TILE + lrow * BPITCH + wn * 64 + lk * 16);

    #pragma unroll 1
    for (int c = 0; c < NC; c++) {
        if (c + 1 < NC) prefetch((c + 1) * KCH);
        __syncthreads();

        uint32_t stb = smb + (uint32_t)((c & 1) * STAGE);
        uint32_t bh[2][4], bl[2][4];
        #pragma unroll
        for (int p = 0; p < 2; p++) {
            uint32_t b = stb + boff + p * 32;
            ldm_x4t(bh[p], b);
            ldm_x4t(bl[p], b + B_TILE);
        }
        #pragma unroll
        for (int mi = 0; mi < 4; mi++) {
            uint32_t ah[4], al[4];
            uint32_t a = stb + aoff + mi * (16 * APITCH);
            ldm_x4(ah, a);
            ldm_x4(al, a + A_TILE);
            #pragma unroll
            for (int ni = 0; ni < 4; ni++) {
                int p = ni >> 1, q = (ni & 1) * 2;
                mma16816(acc[mi][ni], ah, bh[p][q], bh[p][q + 1]);
                mma16816(acc[mi][ni], ah, bl[p][q], bl[p][q + 1]);
                mma16816(acc[mi][ni], al, bh[p][q], bh[p][q + 1]);
            }
        }
        if (c + 1 < NC) store_stage((c + 1) & 1);
    }

    // epilogue: gelu, round to tf32, store fp32
    const int ro  = lane >> 2;
    const int cp2 = (lane & 3) * 2;
    #pragma unroll
    for (int mi = 0; mi < 4; mi++)
        #pragma unroll
        for (int half = 0; half < 2; half++) {
            int lr = wm * 64 + mi * 16 + half * 8 + ro;
            if (m0 + lr < cnt) {
                size_t gr = rowbase + lr;
                float* od = g_H + gr * (size_t)FDIM + n0 + wn * 32 + cp2;
                #pragma unroll
                for (int ni = 0; ni < 4; ni++) {
                    uint32_t t0 = cvt_tf32(gelu_exact(acc[mi][ni][half * 2 + 0]));
                    uint32_t t1 = cvt_tf32(gelu_exact(acc[mi][ni][half * 2 + 1]));
                    uint2 v = make_uint2(t0, t1);
                    *(uint2*)(od + ni * 8) = v;
                }
            }
        }
}

// ---------------- GEMM2: single-pass tf32 mma.sync ------------------------
// Y = w * (H @ W2[e]);  grid (n, m, e).  A smem [m][k] fp32, B smem [n][k] fp32.
__global__ __launch_bounds__(256, 2) void moe_gemm2_kernel(const float* __restrict__ Wglob) {
    constexpr int K  = FDIM;
    constexpr int NT = DDIM;
    constexpr int NC = K / KCH;

    const int e   = blockIdx.z;
    const int cnt = g_count[e];
    const int m0  = blockIdx.y * 128;
    if (m0 >= cnt) return;
    const int n0  = blockIdx.x * 128;
    const int off = g_offset[e];
    const size_t rowbase = (size_t)off + m0;
    const float* Bsrc = Wglob + (size_t)e * K * NT + n0;

    __shared__ __align__(128) char smbuf[2][STAGE2];
    __shared__ float wrow[128];

    const int tid  = threadIdx.x;
    const int warp = tid >> 5, lane = tid & 31;
    const int wm = warp & 1, wn = warp >> 1;    // 2x4 warps: 64m x 32n each

    if (tid < 128) {
        int r = m0 + tid;
        wrow[tid] = (r < cnt) ? g_w_of_row[off + r] : 0.f;
    }

    // A loader: 128 rows x 64B; thread t: row=t>>1, half=t&1 (32B = 2 float4)
    const int a_row = tid >> 1, a_half = tid & 1;
    // B loader: thread t: n = t&127, khalf = t>>7; 8 fp32 (warp-coalesced LDG.32)
    const int b_n = tid & 127, b_kh = tid >> 7;

    size_t ra = rowbase + a_row;
    if (ra >= NROWS) ra = 0;
    const float* aptr = g_H + ra * (size_t)K;

    float4 pa0, pa1;
    float  pb[8];
    auto prefetch = [&](int kc) {
        pa0 = *(const float4*)(aptr + kc + a_half * 8);
        pa1 = *(const float4*)(aptr + kc + a_half * 8 + 4);
        #pragma unroll
        for (int i = 0; i < 8; i++)
            pb[i] = Bsrc[(size_t)(kc + b_kh * 8 + i) * NT + b_n];
    };
    auto store_stage = [&](int stg) {
        char* dst = smbuf[stg];
        *(uint4*)(dst + a_row * PITCH2 + a_half * 32)      = *(uint4*)&pa0;
        *(uint4*)(dst + a_row * PITCH2 + a_half * 32 + 16) = *(uint4*)&pa1;
        uint32_t t[8];
        #pragma unroll
        for (int i = 0; i < 8; i++) t[i] = cvt_tf32(pb[i]);
        *(uint4*)(dst + A_TILE2 + b_n * PITCH2 + b_kh * 32)      = *(uint4*)&t[0];
        *(uint4*)(dst + A_TILE2 + b_n * PITCH2 + b_kh * 32 + 16) = *(uint4*)&t[4];
    };

    prefetch(0);
    store_stage(0);

    float acc[4][4][4];
    #pragma unroll
    for (int i = 0; i < 4; i++)
        #pragma unroll
        for (int j = 0; j < 4; j++)
            #pragma unroll
            for (int q = 0; q < 4; q++) acc[i][j][q] = 0.f;

    const uint32_t smb = smem_u32(smbuf);
    // A frag addressing (per mi, per kstep): rows wm*64+mi*16+(lane&15), byte (lane>>4)*16 + kstep*32
    const uint32_t aoff = (uint32_t)((wm * 64 + (lane & 15)) * PITCH2 + (lane >> 4) * 16);
    // B frag addressing: n row = wn*32 + (lane&7) + ((lane>>4)&1)*8 (+p*16), byte ((lane>>3)&1)*16 + kstep*32
    const int bn_lane = (lane & 7) + ((lane >> 4) & 1) * 8;
    const uint32_t boff = (uint32_t)(A_TILE2 + (wn * 32 + bn_lane) * PITCH2 + ((lane >> 3) & 1) * 16);

    #pragma unroll 1
    for (int c = 0; c < NC; c++) {
        if (c + 1 < NC) prefetch((c + 1) * KCH);
        __syncthreads();

        uint32_t stb = smb + (uint32_t)((c & 1) * STAGE2);
        #pragma unroll
        for (int ks = 0; ks < 2; ks++) {
            uint32_t bf[2][4];
            #pragma unroll
            for (int p = 0; p < 2; p++)
                ldm_x4(bf[p], stb + boff + (uint32_t)(p * 16 * PITCH2 + ks * 32));
            #pragma unroll
            for (int mi = 0; mi < 4; mi++) {
                uint32_t af[4];
                ldm_x4(af, stb + aoff + (uint32_t)(mi * 16 * PITCH2 + ks * 32));
                #pragma unroll
                for (int ni = 0; ni < 4; ni++) {
                    int p = ni >> 1;
                    int q = (ni & 1) * 2;
                    mma_tf32(acc[mi][ni], af, bf[p][q], bf[p][q + 1]);
                }
            }
        }
        if (c + 1 < NC) store_stage((c + 1) & 1);
    }

    // epilogue
    const int ro  = lane >> 2;
    const int cp2 = (lane & 3) * 2;
    #pragma unroll
    for (int mi = 0; mi < 4; mi++)
        #pragma unroll
        for (int half = 0; half < 2; half++) {
            int lr = wm * 64 + mi * 16 + half * 8 + ro;
            if (m0 + lr < cnt) {
                size_t gr = rowbase + lr;
                float w = wrow[lr];
                float* od = g_Y + gr * (size_t)DDIM + n0 + wn * 32 + cp2;
                #pragma unroll
                for (int ni = 0; ni < 4; ni++) {
                    float2 v;
                    v.x = w * acc[mi][ni][half * 2 + 0];
                    v.y = w * acc[mi][ni][half * 2 + 1];
                    *(float2*)(od + ni * 8) = v;
                }
            }
        }
}

// ---------------- combine ----------------
__global__ void combine_kernel(float* __restrict__ out) {
    int idx = blockIdx.x * blockDim.x + threadIdx.x;
    if (idx >= NTOK * (DDIM / 4)) return;
    int n  = idx >> 8;
    int d4 = idx & 255;
    int r0 = g_row_of_token[2 * n + 0];
    int r1 = g_row_of_token[2 * n + 1];
    float4 a = *(const float4*)(g_Y + (size_t)r0 * DDIM + d4 * 4);
    float4 b = *(const float4*)(g_Y + (size_t)r1 * DDIM + d4 * 4);
    float4 o;
    o.x = a.x + b.x; o.y = a.y + b.y; o.z = a.z + b.z; o.w = a.w + b.w;
    ((float4*)out)[idx] = o;
}

// ---------------- launch ----------------
extern "C" void kernel_launch(void* const* d_in, const int* in_sizes, int n_in,
                              void* d_out, int out_size) {
    const float* x  = (const float*)d_in[0];
    const float* Wr = (const float*)d_in[1];
    const float* W1 = (const float*)d_in[2];   // [E][D][F]
    const float* W2 = (const float*)d_in[3];   // [E][F][D]
    float* out = (float*)d_out;

    zero_kernel<<<1, 32>>>();
    router_kernel<<<64, 256>>>(x, Wr);
    prefix_kernel<<<1, 1>>>();
    dispatch_kernel<<<(NTOK + 255) / 256, 256>>>();
    gather_split_x_kernel<<<NROWS, 256>>>(x);
    moe_gemm1_kernel<<<dim3(NROWS / 128, FDIM / 128, NEXP), 256>>>(W1);
    moe_gemm2_kernel<<<dim3(DDIM / 128, NROWS / 128, NEXP), 256>>>(W2);
    combine_kernel<<<(NTOK * (DDIM / 4) + 255) / 256, 256>>>(out);
}

// round 14
// speedup vs baseline: 1.4273x; 1.0465x over previous
#include <cuda_runtime.h>
#include <cuda_bf16.h>
#include <math.h>
#include <stdint.h>

#define NTOK 4096   // B*T
#define DDIM 1024
#define FDIM 4096
#define NEXP 8
#define NROWS (NTOK * 2)   // dispatch rows (top-2)

// ---- shared GEMM tiling (tf32 single-pass, both phases) ----
#define KCH 16
#define PITCH2  80                   // 16 fp32 = 64B padded to 80B (odd 16B units)
#define A_TILE2 (128 * PITCH2)       // 10240  [m][k]
#define B_TILE2 (128 * PITCH2)       // 10240  [n][k]
#define STAGE2  (A_TILE2 + B_TILE2)  // 20480

// ---------------- device scratch (~184MB) ----------------
__device__ int   g_count[NEXP];
__device__ int   g_cursor[NEXP];
__device__ int   g_offset[NEXP];
__device__ int   g_topk_idx[NTOK * 2];
__device__ float g_topk_w[NTOK * 2];
__device__ int   g_token_of_row[NROWS];
__device__ float g_w_of_row[NROWS];
__device__ int   g_row_of_token[NROWS];
__device__ __align__(16) float g_H[(size_t)NROWS * FDIM];   // 134 MB (tf32-rounded)
__device__ __align__(16) float g_Y[(size_t)NROWS * DDIM];   // 33.5 MB

// ---------------- helpers ----------------
__device__ __forceinline__ uint32_t smem_u32(const void* p) {
    uint32_t a;
    asm("{ .reg .u64 t; cvta.to.shared.u64 t, %1; cvt.u32.u64 %0, t; }" : "=r"(a) : "l"(p));
    return a;
}
__device__ __forceinline__ void ldm_x4(uint32_t (&r)[4], uint32_t a) {
    asm volatile("ldmatrix.sync.aligned.m8n8.x4.shared.b16 {%0,%1,%2,%3}, [%4];"
                 : "=r"(r[0]), "=r"(r[1]), "=r"(r[2]), "=r"(r[3]) : "r"(a));
}
__device__ __forceinline__ void mma_tf32(float (&d)[4], const uint32_t (&a)[4],
                                         uint32_t b0, uint32_t b1) {
    asm volatile("mma.sync.aligned.m16n8k8.row.col.f32.tf32.tf32.f32 "
                 "{%0,%1,%2,%3}, {%4,%5,%6,%7}, {%8,%9}, {%0,%1,%2,%3};"
                 : "+f"(d[0]), "+f"(d[1]), "+f"(d[2]), "+f"(d[3])
                 : "r"(a[0]), "r"(a[1]), "r"(a[2]), "r"(a[3]), "r"(b0), "r"(b1));
}
__device__ __forceinline__ uint32_t cvt_tf32(float v) {
    uint32_t r;
    asm("cvt.rna.tf32.f32 %0, %1;" : "=r"(r) : "f"(v));
    return r;
}
__device__ __forceinline__ float gelu_exact(float v) {
    return 0.5f * v * (1.0f + erff(v * 0.70710678118654752440f));
}

// ---------------- K0-K3: routing (unchanged, proven) ----------------
__global__ void zero_kernel() {
    int t = threadIdx.x;
    if (t < NEXP) { g_count[t] = 0; g_cursor[t] = 0; }
}

__global__ void router_kernel(const float* __restrict__ x,
                              const float* __restrict__ Wr) {
    int gwarp  = (blockIdx.x * blockDim.x + threadIdx.x) >> 5;
    int lane   = threadIdx.x & 31;
    int nwarps = (gridDim.x * blockDim.x) >> 5;
    for (int n = gwarp; n < NTOK; n += nwarps) {
        const float* xr = x + (size_t)n * DDIM;
        float acc[NEXP];
        #pragma unroll
        for (int e = 0; e < NEXP; e++) acc[e] = 0.f;
        for (int d = lane; d < DDIM; d += 32) {
            float xv = xr[d];
            const float* wr = Wr + (size_t)d * NEXP;
            float4 w0 = *(const float4*)(wr);
            float4 w1 = *(const float4*)(wr + 4);
            acc[0] = fmaf(xv, w0.x, acc[0]); acc[1] = fmaf(xv, w0.y, acc[1]);
            acc[2] = fmaf(xv, w0.z, acc[2]); acc[3] = fmaf(xv, w0.w, acc[3]);
            acc[4] = fmaf(xv, w1.x, acc[4]); acc[5] = fmaf(xv, w1.y, acc[5]);
            acc[6] = fmaf(xv, w1.z, acc[6]); acc[7] = fmaf(xv, w1.w, acc[7]);
        }
        #pragma unroll
        for (int e = 0; e < NEXP; e++)
            #pragma unroll
            for (int o = 16; o > 0; o >>= 1)
                acc[e] += __shfl_xor_sync(0xFFFFFFFFu, acc[e], o);
        if (lane == 0) {
            int i0 = 0; float v0 = acc[0];
            #pragma unroll
            for (int e = 1; e < NEXP; e++)
                if (acc[e] > v0) { v0 = acc[e]; i0 = e; }
            int i1 = -1; float v1 = -3.4e38f;
            #pragma unroll
            for (int e = 0; e < NEXP; e++)
                if (e != i0 && acc[e] > v1) { v1 = acc[e]; i1 = e; }
            float e1 = __expf(v1 - v0);
            float inv = 1.0f / (1.0f + e1);
            g_topk_idx[2 * n + 0] = i0;
            g_topk_idx[2 * n + 1] = i1;
            g_topk_w[2 * n + 0] = inv;
            g_topk_w[2 * n + 1] = e1 * inv;
            atomicAdd(&g_count[i0], 1);
            atomicAdd(&g_count[i1], 1);
        }
    }
}

__global__ void prefix_kernel() {
    int s = 0;
    for (int e = 0; e < NEXP; e++) { g_offset[e] = s; s += g_count[e]; }
}

__global__ void dispatch_kernel() {
    int n = blockIdx.x * blockDim.x + threadIdx.x;
    if (n >= NTOK) return;
    #pragma unroll
    for (int s = 0; s < 2; s++) {
        int e   = g_topk_idx[2 * n + s];
        int pos = atomicAdd(&g_cursor[e], 1);
        int row = g_offset[e] + pos;
        g_token_of_row[row] = n;
        g_w_of_row[row]     = g_topk_w[2 * n + s];
        g_row_of_token[2 * n + s] = row;
    }
}

// ---------------- GEMM (tf32 single-pass, both phases) --------------------
// PH1: H(tf32-rounded fp32) = gelu(X_gathered @ W1[e]);  grid (m, n, e)
// PH2: Y = w * (H @ W2[e]);                               grid (n, m, e)
// A smem [m][k] fp32(tf32), B smem [n][k] fp32(tf32); mma.m16n8k8.tf32.
template<bool PH1>
__global__ __launch_bounds__(256, 2) void moe_gemm_kernel(const float* __restrict__ Xglob,
                                                          const float* __restrict__ Wglob) {
    constexpr int K  = PH1 ? DDIM : FDIM;
    constexpr int NT = PH1 ? FDIM : DDIM;
    constexpr int NC = K / KCH;

    const int e   = blockIdx.z;
    const int cnt = g_count[e];
    const int m0  = (PH1 ? blockIdx.x : blockIdx.y) * 128;
    if (m0 >= cnt) return;
    const int n0  = (PH1 ? blockIdx.y : blockIdx.x) * 128;
    const int off = g_offset[e];
    const size_t rowbase = (size_t)off + m0;
    const float* Bsrc = Wglob + (size_t)e * K * NT + n0;

    __shared__ __align__(128) char smbuf[2][STAGE2];
    __shared__ int   toks[128];
    __shared__ float wrow[128];

    const int tid  = threadIdx.x;
    const int warp = tid >> 5, lane = tid & 31;
    const int wm = warp & 1, wn = warp >> 1;    // 2x4 warps: 64m x 32n each

    if (tid < 128) {
        int r = m0 + tid;
        if (PH1) toks[tid] = (r < cnt) ? g_token_of_row[off + r] : g_token_of_row[off];
        else     wrow[tid] = (r < cnt) ? g_w_of_row[off + r] : 0.f;
    }
    __syncthreads();

    // A loader: 128 rows x 64B; thread t: row=t>>1, half=t&1 (16 fp32 per thread)
    const int a_row = tid >> 1, a_half = tid & 1;
    // B loader: thread t: n = t&127, khalf = t>>7; 8 strided fp32
    const int b_n = tid & 127, b_kh = tid >> 7;

    const float* aptr;
    if (PH1) {
        aptr = Xglob + (size_t)toks[a_row] * DDIM;
    } else {
        size_t ra = rowbase + a_row;
        if (ra >= NROWS) ra = 0;
        aptr = Xglob + ra * (size_t)FDIM;
    }

    float4 pa0, pa1;
    float  pb[8];
    auto prefetch = [&](int kc) {
        pa0 = *(const float4*)(aptr + kc + a_half * 8);
        pa1 = *(const float4*)(aptr + kc + a_half * 8 + 4);
        #pragma unroll
        for (int i = 0; i < 8; i++)
            pb[i] = Bsrc[(size_t)(kc + b_kh * 8 + i) * NT + b_n];
    };
    auto store_stage = [&](int stg) {
        char* dst = smbuf[stg];
        if (PH1) {   // round gathered X to tf32
            uint4 ta, tb;
            ta.x = cvt_tf32(pa0.x); ta.y = cvt_tf32(pa0.y);
            ta.z = cvt_tf32(pa0.z); ta.w = cvt_tf32(pa0.w);
            tb.x = cvt_tf32(pa1.x); tb.y = cvt_tf32(pa1.y);
            tb.z = cvt_tf32(pa1.z); tb.w = cvt_tf32(pa1.w);
            *(uint4*)(dst + a_row * PITCH2 + a_half * 32)      = ta;
            *(uint4*)(dst + a_row * PITCH2 + a_half * 32 + 16) = tb;
        } else {     // H already tf32-rounded
            *(uint4*)(dst + a_row * PITCH2 + a_half * 32)      = *(uint4*)&pa0;
            *(uint4*)(dst + a_row * PITCH2 + a_half * 32 + 16) = *(uint4*)&pa1;
        }
        uint32_t t[8];
        #pragma unroll
        for (int i = 0; i < 8; i++) t[i] = cvt_tf32(pb[i]);
        *(uint4*)(dst + A_TILE2 + b_n * PITCH2 + b_kh * 32)      = *(uint4*)&t[0];
        *(uint4*)(dst + A_TILE2 + b_n * PITCH2 + b_kh * 32 + 16) = *(uint4*)&t[4];
    };

    prefetch(0);
    store_stage(0);

    float acc[4][4][4];
    #pragma unroll
    for (int i = 0; i < 4; i++)
        #pragma unroll
        for (int j = 0; j < 4; j++)
            #pragma unroll
            for (int q = 0; q < 4; q++) acc[i][j][q] = 0.f;

    const uint32_t smb = smem_u32(smbuf);
    const uint32_t aoff = (uint32_t)((wm * 64 + (lane & 15)) * PITCH2 + (lane >> 4) * 16);
    const int bn_lane = (lane & 7) + ((lane >> 4) & 1) * 8;
    const uint32_t boff = (uint32_t)(A_TILE2 + (wn * 32 + bn_lane) * PITCH2 + ((lane >> 3) & 1) * 16);

    #pragma unroll 1
    for (int c = 0; c < NC; c++) {
        if (c + 1 < NC) prefetch((c + 1) * KCH);
        __syncthreads();

        uint32_t stb = smb + (uint32_t)((c & 1) * STAGE2);
        #pragma unroll
        for (int ks = 0; ks < 2; ks++) {
            uint32_t bf[2][4];
            #pragma unroll
            for (int p = 0; p < 2; p++)
                ldm_x4(bf[p], stb + boff + (uint32_t)(p * 16 * PITCH2 + ks * 32));
            #pragma unroll
            for (int mi = 0; mi < 4; mi++) {
                uint32_t af[4];
                ldm_x4(af, stb + aoff + (uint32_t)(mi * 16 * PITCH2 + ks * 32));
                #pragma unroll
                for (int ni = 0; ni < 4; ni++) {
                    int p = ni >> 1;
                    int q = (ni & 1) * 2;
                    mma_tf32(acc[mi][ni], af, bf[p][q], bf[p][q + 1]);
                }
            }
        }
        if (c + 1 < NC) store_stage((c + 1) & 1);
    }

    // ---------------- epilogue ----------------
    const int ro  = lane >> 2;
    const int cp2 = (lane & 3) * 2;
    #pragma unroll
    for (int mi = 0; mi < 4; mi++)
        #pragma unroll
        for (int half = 0; half < 2; half++) {
            int lr = wm * 64 + mi * 16 + half * 8 + ro;
            if (m0 + lr < cnt) {
                size_t gr = rowbase + lr;
                if (PH1) {
                    float* od = g_H + gr * (size_t)FDIM + n0 + wn * 32 + cp2;
                    #pragma unroll
                    for (int ni = 0; ni < 4; ni++) {
                        uint32_t t0 = cvt_tf32(gelu_exact(acc[mi][ni][half * 2 + 0]));
                        uint32_t t1 = cvt_tf32(gelu_exact(acc[mi][ni][half * 2 + 1]));
                        *(uint2*)(od + ni * 8) = make_uint2(t0, t1);
                    }
                } else {
                    float w = wrow[lr];
                    float* od = g_Y + gr * (size_t)DDIM + n0 + wn * 32 + cp2;
                    #pragma unroll
                    for (int ni = 0; ni < 4; ni++) {
                        float2 v;
                        v.x = w * acc[mi][ni][half * 2 + 0];
                        v.y = w * acc[mi][ni][half * 2 + 1];
                        *(float2*)(od + ni * 8) = v;
                    }
                }
            }
        }
}

// ---------------- combine ----------------
__global__ void combine_kernel(float* __restrict__ out) {
    int idx = blockIdx.x * blockDim.x + threadIdx.x;
    if (idx >= NTOK * (DDIM / 4)) return;
    int n  = idx >> 8;
    int d4 = idx & 255;
    int r0 = g_row_of_token[2 * n + 0];
    int r1 = g_row_of_token[2 * n + 1];
    float4 a = *(const float4*)(g_Y + (size_t)r0 * DDIM + d4 * 4);
    float4 b = *(const float4*)(g_Y + (size_t)r1 * DDIM + d4 * 4);
    float4 o;
    o.x = a.x + b.x; o.y = a.y + b.y; o.z = a.z + b.z; o.w = a.w + b.w;
    ((float4*)out)[idx] = o;
}

// ---------------- launch ----------------
extern "C" void kernel_launch(void* const* d_in, const int* in_sizes, int n_in,
                              void* d_out, int out_size) {
    const float* x  = (const float*)d_in[0];
    const float* Wr = (const float*)d_in[1];
    const float* W1 = (const float*)d_in[2];   // [E][D][F]
    const float* W2 = (const float*)d_in[3];   // [E][F][D]
    float* out = (float*)d_out;

    zero_kernel<<<1, 32>>>();
    router_kernel<<<64, 256>>>(x, Wr);
    prefix_kernel<<<1, 1>>>();
    dispatch_kernel<<<(NTOK + 255) / 256, 256>>>();
    moe_gemm_kernel<true><<<dim3(NROWS / 128, FDIM / 128, NEXP), 256>>>(x, W1);
    float* hptr = nullptr;
    cudaGetSymbolAddress((void**)&hptr, g_H);
    moe_gemm_kernel<false><<<dim3(DDIM / 128, NROWS / 128, NEXP), 256>>>(hptr, W2);
    combine_kernel<<<(NTOK * (DDIM / 4) + 255) / 256, 256>>>(out);
}

// round 15
// speedup vs baseline: 1.9449x; 1.3626x over previous
#include <cuda_runtime.h>
#include <cuda_fp16.h>
#include <math.h>
#include <stdint.h>

#define NTOK 4096   // B*T
#define DDIM 1024
#define FDIM 4096
#define NEXP 8
#define NROWS (NTOK * 2)   // dispatch rows (top-2)

// GEMM tiling: 128x128 CTA tile, K-chunk 16, fp16 operands, 2-stage static smem
#define KCH 16
#define APITCH 48                    // 16 fp16 = 32B padded to 48B (odd 16B units)
#define BPITCH 272                   // 128 fp16 = 256B padded to 272B
#define A_TILE (128 * APITCH)        // 6144
#define B_TILE (KCH * BPITCH)        // 4352
#define STAGE  (A_TILE + B_TILE)     // 10496

// ---------------- device scratch (~117MB) ----------------
__device__ int   g_count[NEXP];
__device__ int   g_cursor[NEXP];
__device__ int   g_offset[NEXP];
__device__ int   g_topk_idx[NTOK * 2];
__device__ float g_topk_w[NTOK * 2];
__device__ int   g_token_of_row[NROWS];
__device__ float g_w_of_row[NROWS];
__device__ int   g_row_of_token[NROWS];
__device__ __align__(16) __half g_Xh[(size_t)NROWS * DDIM];   // 16 MB (gathered, fp16)
__device__ __align__(16) __half g_Hh[(size_t)NROWS * FDIM];   // 67 MB (fp16)
__device__ __align__(16) float  g_Y[(size_t)NROWS * DDIM];    // 33.5 MB

// ---------------- helpers ----------------
__device__ __forceinline__ uint32_t smem_u32(const void* p) {
    uint32_t a;
    asm("{ .reg .u64 t; cvta.to.shared.u64 t, %1; cvt.u32.u64 %0, t; }" : "=r"(a) : "l"(p));
    return a;
}
__device__ __forceinline__ void ldm_x4(uint32_t (&r)[4], uint32_t a) {
    asm volatile("ldmatrix.sync.aligned.m8n8.x4.shared.b16 {%0,%1,%2,%3}, [%4];"
                 : "=r"(r[0]), "=r"(r[1]), "=r"(r[2]), "=r"(r[3]) : "r"(a));
}
__device__ __forceinline__ void ldm_x4t(uint32_t (&r)[4], uint32_t a) {
    asm volatile("ldmatrix.sync.aligned.m8n8.x4.trans.shared.b16 {%0,%1,%2,%3}, [%4];"
                 : "=r"(r[0]), "=r"(r[1]), "=r"(r[2]), "=r"(r[3]) : "r"(a));
}
__device__ __forceinline__ void mma16816f(float (&d)[4], const uint32_t (&a)[4],
                                          uint32_t b0, uint32_t b1) {
    asm volatile("mma.sync.aligned.m16n8k16.row.col.f32.f16.f16.f32 "
                 "{%0,%1,%2,%3}, {%4,%5,%6,%7}, {%8,%9}, {%0,%1,%2,%3};"
                 : "+f"(d[0]), "+f"(d[1]), "+f"(d[2]), "+f"(d[3])
                 : "r"(a[0]), "r"(a[1]), "r"(a[2]), "r"(a[3]), "r"(b0), "r"(b1));
}
__device__ __forceinline__ uint32_t f2h2(float a, float b) {
    __half2 h = __floats2half2_rn(a, b);
    return *reinterpret_cast<uint32_t*>(&h);
}
__device__ __forceinline__ float gelu_exact(float v) {
    return 0.5f * v * (1.0f + erff(v * 0.70710678118654752440f));
}

// ---------------- K0-K3: routing (unchanged, proven) ----------------
__global__ void zero_kernel() {
    int t = threadIdx.x;
    if (t < NEXP) { g_count[t] = 0; g_cursor[t] = 0; }
}

__global__ void router_kernel(const float* __restrict__ x,
                              const float* __restrict__ Wr) {
    int gwarp  = (blockIdx.x * blockDim.x + threadIdx.x) >> 5;
    int lane   = threadIdx.x & 31;
    int nwarps = (gridDim.x * blockDim.x) >> 5;
    for (int n = gwarp; n < NTOK; n += nwarps) {
        const float* xr = x + (size_t)n * DDIM;
        float acc[NEXP];
        #pragma unroll
        for (int e = 0; e < NEXP; e++) acc[e] = 0.f;
        for (int d = lane; d < DDIM; d += 32) {
            float xv = xr[d];
            const float* wr = Wr + (size_t)d * NEXP;
            float4 w0 = *(const float4*)(wr);
            float4 w1 = *(const float4*)(wr + 4);
            acc[0] = fmaf(xv, w0.x, acc[0]); acc[1] = fmaf(xv, w0.y, acc[1]);
            acc[2] = fmaf(xv, w0.z, acc[2]); acc[3] = fmaf(xv, w0.w, acc[3]);
            acc[4] = fmaf(xv, w1.x, acc[4]); acc[5] = fmaf(xv, w1.y, acc[5]);
            acc[6] = fmaf(xv, w1.z, acc[6]); acc[7] = fmaf(xv, w1.w, acc[7]);
        }
        #pragma unroll
        for (int e = 0; e < NEXP; e++)
            #pragma unroll
            for (int o = 16; o > 0; o >>= 1)
                acc[e] += __shfl_xor_sync(0xFFFFFFFFu, acc[e], o);
        if (lane == 0) {
            int i0 = 0; float v0 = acc[0];
            #pragma unroll
            for (int e = 1; e < NEXP; e++)
                if (acc[e] > v0) { v0 = acc[e]; i0 = e; }
            int i1 = -1; float v1 = -3.4e38f;
            #pragma unroll
            for (int e = 0; e < NEXP; e++)
                if (e != i0 && acc[e] > v1) { v1 = acc[e]; i1 = e; }
            float e1 = __expf(v1 - v0);
            float inv = 1.0f / (1.0f + e1);
            g_topk_idx[2 * n + 0] = i0;
            g_topk_idx[2 * n + 1] = i1;
            g_topk_w[2 * n + 0] = inv;
            g_topk_w[2 * n + 1] = e1 * inv;
            atomicAdd(&g_count[i0], 1);
            atomicAdd(&g_count[i1], 1);
        }
    }
}

__global__ void prefix_kernel() {
    int s = 0;
    for (int e = 0; e < NEXP; e++) { g_offset[e] = s; s += g_count[e]; }
}

__global__ void dispatch_kernel() {
    int n = blockIdx.x * blockDim.x + threadIdx.x;
    if (n >= NTOK) return;
    #pragma unroll
    for (int s = 0; s < 2; s++) {
        int e   = g_topk_idx[2 * n + s];
        int pos = atomicAdd(&g_cursor[e], 1);
        int row = g_offset[e] + pos;
        g_token_of_row[row] = n;
        g_w_of_row[row]     = g_topk_w[2 * n + s];
        g_row_of_token[2 * n + s] = row;
    }
}

// ---------------- K4: gather X -> fp16 (expert-compact rows) --------------
__global__ void gather_x_kernel(const float* __restrict__ x) {
    int r = blockIdx.x;
    int t = g_token_of_row[r];
    float4 v = ((const float4*)(x + (size_t)t * DDIM))[threadIdx.x];
    uint2 o = make_uint2(f2h2(v.x, v.y), f2h2(v.z, v.w));
    ((uint2*)(g_Xh + (size_t)r * DDIM))[threadIdx.x] = o;
}

// ---------------- GEMM: fp16 mma.sync m16n8k16 (R12 engine, single-pass) --
// PH1: H(fp16) = gelu(Xh @ W1[e]);  grid (m, n, e)
// PH2: Y = w * (Hh @ W2[e]);        grid (n, m, e)
template<bool PH1>
__global__ __launch_bounds__(256, 2) void moe_gemm_kernel(const __half* __restrict__ Aglob,
                                                          const float* __restrict__ Wglob) {
    constexpr int K  = PH1 ? DDIM : FDIM;
    constexpr int NT = PH1 ? FDIM : DDIM;
    constexpr int NC = K / KCH;

    const int e   = blockIdx.z;
    const int cnt = g_count[e];
    const int m0  = (PH1 ? blockIdx.x : blockIdx.y) * 128;
    if (m0 >= cnt) return;
    const int n0  = (PH1 ? blockIdx.y : blockIdx.x) * 128;
    const int off = g_offset[e];
    const size_t rowbase = (size_t)off + m0;
    const float* Bsrc = Wglob + (size_t)e * K * NT + n0;

    __shared__ __align__(128) char smbuf[2][STAGE];
    __shared__ float wrow[128];

    const int tid  = threadIdx.x;
    const int warp = tid >> 5, lane = tid & 31;
    const int wm = warp & 1, wn = warp >> 1;    // 2x4 warps: 64m x 32n each

    if (!PH1 && tid < 128) {
        int r = m0 + tid;
        wrow[tid] = (r < cnt) ? g_w_of_row[off + r] : 0.f;
    }

    // loader roles: A 128 rows x 2 segs(8 fp16); B 16 k-rows x 16 segs(8 fp32->fp16)
    const int a_row = tid >> 1, a_seg = tid & 1;
    const int b_k   = tid >> 4, b_seg = tid & 15;

    size_t ra = rowbase + a_row;
    if (ra >= NROWS) ra = 0;   // clamp (values discarded via epilogue bounds)
    const __half* aptr = Aglob + ra * (size_t)K;

    uint4  pah;
    float4 pb0, pb1;
    auto prefetch = [&](int kc) {
        pah = *(const uint4*)(aptr + kc + a_seg * 8);
        pb0 = *(const float4*)(Bsrc + (size_t)(kc + b_k) * NT + b_seg * 8);
        pb1 = *(const float4*)(Bsrc + (size_t)(kc + b_k) * NT + b_seg * 8 + 4);
    };
    auto store_stage = [&](int stg) {
        char* dst = smbuf[stg];
        *(uint4*)(dst + a_row * APITCH + a_seg * 16) = pah;
        uint4 hb;
        hb.x = f2h2(pb0.x, pb0.y); hb.y = f2h2(pb0.z, pb0.w);
        hb.z = f2h2(pb1.x, pb1.y); hb.w = f2h2(pb1.z, pb1.w);
        *(uint4*)(dst + A_TILE + b_k * BPITCH + b_seg * 16) = hb;
    };

    prefetch(0);
    store_stage(0);

    float acc[4][4][4];
    #pragma unroll
    for (int i = 0; i < 4; i++)
        #pragma unroll
        for (int j = 0; j < 4; j++)
            #pragma unroll
            for (int q = 0; q < 4; q++) acc[i][j][q] = 0.f;

    const uint32_t smb = smem_u32(smbuf);
    const int lrow = lane & 15;
    const int lk   = lane >> 4;
    const uint32_t aoff = (uint32_t)((wm * 64 + lrow) * APITCH + lk * 16);
    const uint32_t boff = (uint32_t)(A_TILE + lrow * BPITCH + wn * 64 + lk * 16);

    #pragma unroll 1
    for (int c = 0; c < NC; c++) {
        if (c + 1 < NC) prefetch((c + 1) * KCH);   // LDG issued before barrier
        __syncthreads();   // stage c&1 stores visible; stage (c+1)&1 readers done

        uint32_t stb = smb + (uint32_t)((c & 1) * STAGE);
        uint32_t bh[2][4];
        #pragma unroll
        for (int p = 0; p < 2; p++)
            ldm_x4t(bh[p], stb + boff + p * 32);
        #pragma unroll
        for (int mi = 0; mi < 4; mi++) {
            uint32_t ah[4];
            ldm_x4(ah, stb + aoff + mi * (16 * APITCH));
            #pragma unroll
            for (int ni = 0; ni < 4; ni++) {
                int p = ni >> 1, q = (ni & 1) * 2;
                mma16816f(acc[mi][ni], ah, bh[p][q], bh[p][q + 1]);
            }
        }
        if (c + 1 < NC) store_stage((c + 1) & 1);
    }

    // ---------------- epilogue ----------------
    const int ro  = lane >> 2;
    const int cp2 = (lane & 3) * 2;
    #pragma unroll
    for (int mi = 0; mi < 4; mi++)
        #pragma unroll
        for (int half = 0; half < 2; half++) {
            int lr = wm * 64 + mi * 16 + half * 8 + ro;
            if (m0 + lr < cnt) {
                size_t gr = rowbase + lr;
                if (PH1) {
                    __half* od = g_Hh + gr * (size_t)FDIM + n0 + wn * 32 + cp2;
                    #pragma unroll
                    for (int ni = 0; ni < 4; ni++) {
                        float f0 = gelu_exact(acc[mi][ni][half * 2 + 0]);
                        float f1 = gelu_exact(acc[mi][ni][half * 2 + 1]);
                        *(uint32_t*)(od + ni * 8) = f2h2(f0, f1);
                    }
                } else {
                    float w = wrow[lr];
                    float* od = g_Y + gr * (size_t)DDIM + n0 + wn * 32 + cp2;
                    #pragma unroll
                    for (int ni = 0; ni < 4; ni++) {
                        float2 v;
                        v.x = w * acc[mi][ni][half * 2 + 0];
                        v.y = w * acc[mi][ni][half * 2 + 1];
                        *(float2*)(od + ni * 8) = v;
                    }
                }
            }
        }
}

// ---------------- combine ----------------
__global__ void combine_kernel(float* __restrict__ out) {
    int idx = blockIdx.x * blockDim.x + threadIdx.x;
    if (idx >= NTOK * (DDIM / 4)) return;
    int n  = idx >> 8;
    int d4 = idx & 255;
    int r0 = g_row_of_token[2 * n + 0];
    int r1 = g_row_of_token[2 * n + 1];
    float4 a = *(const float4*)(g_Y + (size_t)r0 * DDIM + d4 * 4);
    float4 b = *(const float4*)(g_Y + (size_t)r1 * DDIM + d4 * 4);
    float4 o;
    o.x = a.x + b.x; o.y = a.y + b.y; o.z = a.z + b.z; o.w = a.w + b.w;
    ((float4*)out)[idx] = o;
}

// ---------------- launch ----------------
extern "C" void kernel_launch(void* const* d_in, const int* in_sizes, int n_in,
                              void* d_out, int out_size) {
    const float* x  = (const float*)d_in[0];
    const float* Wr = (const float*)d_in[1];
    const float* W1 = (const float*)d_in[2];   // [E][D][F]
    const float* W2 = (const float*)d_in[3];   // [E][F][D]
    float* out = (float*)d_out;

    zero_kernel<<<1, 32>>>();
    router_kernel<<<128, 256>>>(x, Wr);
    prefix_kernel<<<1, 1>>>();
    dispatch_kernel<<<(NTOK + 255) / 256, 256>>>();
    gather_x_kernel<<<NROWS, 256>>>(x);

    __half* xh = nullptr;
    __half* hh = nullptr;
    cudaGetSymbolAddress((void**)&xh, g_Xh);
    cudaGetSymbolAddress((void**)&hh, g_Hh);
    moe_gemm_kernel<true><<<dim3(NROWS / 128, FDIM / 128, NEXP), 256>>>(xh, W1);
    moe_gemm_kernel<false><<<dim3(DDIM / 128, NROWS / 128, NEXP), 256>>>(hh, W2);
    combine_kernel<<<(NTOK * (DDIM / 4) + 255) / 256, 256>>>(out);
}